// round 16
// baseline (speedup 1.0000x reference)
#include <cuda_runtime.h>
#include <float.h>

#define VOCAB 8000
#define C 256
#define P 8
#define BB 16
#define LL 2048
#define T 32                  // positions per block
#define ROWS (T + 2*P)        // 48 window-row token ids
#define THREADS 256
#define GP 8                  // positions per 64-thread group

__device__ __forceinline__ void cp_async4(void* smem, const void* gptr) {
    unsigned s = (unsigned)__cvta_generic_to_shared(smem);
    asm volatile("cp.async.ca.shared.global [%0], [%1], 4;" :: "r"(s), "l"(gptr));
}
__device__ __forceinline__ float4 mul4(float4 a, float4 w) {
    return make_float4(a.x * w.x, a.y * w.y, a.z * w.z, a.w * w.w);
}
__device__ __forceinline__ float4 max4(float4 a, float4 b) {
    return make_float4(fmaxf(a.x, b.x), fmaxf(a.y, b.y),
                       fmaxf(a.z, b.z), fmaxf(a.w, b.w));
}

__global__ __launch_bounds__(THREADS, 2)
void gnn_kernel(const int* __restrict__ ids,
                const float* __restrict__ emb,
                const float* __restrict__ ew,
                const float* __restrict__ nw,
                float* __restrict__ out)
{
    __shared__ __align__(16) float W_s[T * 16];     // edge weights [pos][j]
    __shared__ float  NN_s[T];                      // node weights
    __shared__ int    NX_s[ROWS];                   // window-row token ids
    __shared__ float4 Acc_s[3 * 64];                // partials from groups 1..3

    const int b  = blockIdx.y;
    const int l0 = blockIdx.x * T;
    const int* idrow = ids + b * LL;
    const int tid  = threadIdx.x;
    const int g    = tid >> 6;          // position-group 0..3 (2 warps each)
    const int ct   = tid & 63;          // lane in group -> channels 4ct..4ct+3
    const int p0   = g * GP;

    // ---- stage token ids (block-wide, once) ----
    if (tid < ROWS) {
        int p = l0 - P + tid;
        NX_s[tid] = (p >= 0 && p < LL) ? idrow[p] : 0;   // emb row 0 is all-zero
    }
    __syncthreads();

    // ---- own-group weight gather: thread covers entries 2*tid, 2*tid+1 ----
    {
        int e0 = 2 * tid, e1 = 2 * tid + 1;
        int t0 = e0 >> 4, j0 = e0 & 15, k0 = j0 + (j0 >= P);
        int t1 = e1 >> 4, j1 = e1 & 15, k1 = j1 + (j1 >= P);
        // nx==0 -> emb row 0 all-zero -> product 0 regardless of weight value
        cp_async4(&W_s[e0], ew + (size_t)NX_s[t0 + P] * VOCAB + NX_s[t0 + k0]);
        cp_async4(&W_s[e1], ew + (size_t)NX_s[t1 + P] * VOCAB + NX_s[t1 + k1]);
        if (ct < GP)
            cp_async4(&NN_s[p0 + ct], nw + NX_s[p0 + ct + P]);
    }
    asm volatile("cp.async.commit_group;" ::: "memory");

    // ---- float4 register window init (covers the gather latency) ----
    const float4* __restrict__ e4 = (const float4*)emb;
    float4 win[17];
    #pragma unroll
    for (int k = 0; k < 17; k++)
        win[k] = e4[(size_t)NX_s[p0 + k] * (C / 4) + ct];
    float4 pf0 = e4[(size_t)NX_s[p0 + 17] * (C / 4) + ct];
    float4 pf1 = e4[(size_t)NX_s[p0 + 18] * (C / 4) + ct];

    // own gather done + group-local barrier (64 threads own their W region)
    asm volatile("cp.async.wait_group 0;" ::: "memory");
    asm volatile("bar.sync %0, %1;" :: "r"(g + 1), "r"(64) : "memory");

    float4 acc = make_float4(0.f, 0.f, 0.f, 0.f);

    #pragma unroll
    for (int tt = 0; tt < GP; tt++) {
        // refill LDG (rows p0+19+tt; rows beyond p0+23 never consumed)
        float4 newv = pf1;
        if (tt <= 4)
            newv = e4[(size_t)NX_s[p0 + 19 + tt] * (C / 4) + ct];

        const float4* wv = (const float4*)(W_s + (p0 + tt) * 16);
        float4 wa = wv[0], wb = wv[1], wc = wv[2], wd = wv[3];
        float nn = NN_s[p0 + tt];

        // two interleaved max chains per channel (float4-wide)
        float4 m0, m1;
        #define VW(j) win[(tt + (j) + ((j) >= 8)) % 17]
        m0 = mul4(VW(0),  make_float4(wa.x, wa.x, wa.x, wa.x));
        m1 = mul4(VW(1),  make_float4(wa.y, wa.y, wa.y, wa.y));
        #define STEP(j, w, m) m = max4(m, mul4(VW(j), make_float4(w, w, w, w)));
        STEP(2,  wa.z, m0) STEP(3,  wa.w, m1)
        STEP(4,  wb.x, m0) STEP(5,  wb.y, m1) STEP(6,  wb.z, m0) STEP(7,  wb.w, m1)
        STEP(8,  wc.x, m0) STEP(9,  wc.y, m1) STEP(10, wc.z, m0) STEP(11, wc.w, m1)
        STEP(12, wd.x, m0) STEP(13, wd.y, m1) STEP(14, wd.z, m0) STEP(15, wd.w, m1)
        #undef STEP
        float4 m = max4(m0, m1);

        float4 rn = win[(tt + 8) % 17];
        acc.x += fmaf(nn, rn.x - m.x, m.x);   // (1-nn)*m + nn*rn
        acc.y += fmaf(nn, rn.y - m.y, m.y);
        acc.z += fmaf(nn, rn.z - m.z, m.z);
        acc.w += fmaf(nn, rn.w - m.w, m.w);
        #undef VW

        // slide window through 2-deep prefetch ring (register renaming)
        win[tt % 17] = pf0;
        pf0 = pf1;
        pf1 = newv;
    }

    // ---- combine the 4 position-groups in SMEM, then 262K atomics total ----
    if (g > 0)
        Acc_s[(g - 1) * 64 + ct] = acc;
    __syncthreads();
    if (g == 0) {
        float4 a1 = Acc_s[0 * 64 + ct];
        float4 a2 = Acc_s[1 * 64 + ct];
        float4 a3 = Acc_s[2 * 64 + ct];
        acc.x += a1.x + a2.x + a3.x;
        acc.y += a1.y + a2.y + a3.y;
        acc.z += a1.z + a2.z + a3.z;
        acc.w += a1.w + a2.w + a3.w;
        float* o = out + b * C + 4 * ct;
        atomicAdd(o + 0, acc.x);
        atomicAdd(o + 1, acc.y);
        atomicAdd(o + 2, acc.z);
        atomicAdd(o + 3, acc.w);
    }
}

extern "C" void kernel_launch(void* const* d_in, const int* in_sizes, int n_in,
                              void* d_out, int out_size) {
    const int*   ids = (const int*)  d_in[0];
    const float* emb = (const float*)d_in[1];
    const float* ew  = (const float*)d_in[2];
    const float* nw  = (const float*)d_in[3];
    float* out = (float*)d_out;

    // graph memset node zeroes d_out (poisoned to 0xAA by the harness)
    cudaMemsetAsync(out, 0, (size_t)out_size * sizeof(float));

    dim3 grid(LL / T, BB);
    gnn_kernel<<<grid, THREADS>>>(ids, emb, ew, nw, out);
}

// round 17
// speedup vs baseline: 1.1096x; 1.1096x over previous
#include <cuda_runtime.h>
#include <float.h>

#define VOCAB 8000
#define C 256
#define P 8
#define BB 16
#define LL 2048
#define T 32                  // positions per block tile
#define ROWS (T + 2*P)        // 48 window-row token ids
#define THREADS 256
#define D 4                   // emb prefetch ring depth

__global__ __launch_bounds__(THREADS, 4)
void gnn_kernel(const int* __restrict__ ids,
                const float* __restrict__ emb,
                const float* __restrict__ ew,
                const float* __restrict__ nw,
                float* __restrict__ out)
{
    __shared__ __align__(16) float W_s[T * 16];   // edge weights [pos][j]
    __shared__ float NN_s[T];                     // node weights
    __shared__ int   NX_s[ROWS];                  // window-row token ids

    const int b  = blockIdx.y;
    const int l0 = blockIdx.x * T;
    const int* idrow = ids + b * LL;
    const int tid = threadIdx.x;
    const int ct  = tid;                          // this thread's channel

    // ---- stage token ids ----
    if (tid < ROWS) {
        int p = l0 - P + tid;
        NX_s[tid] = (p >= 0 && p < LL) ? idrow[p] : 0;   // emb row 0 is all-zero
    }
    __syncthreads();

    // ---- edge-weight gather via ld.global.cg: L2-only, 32B-sector DRAM fetch
    //      (not 128B line) -> 4x less DRAM traffic. Issued BEFORE window init
    //      so the window LDGs cover the random-DRAM latency.
    const int e0 = 2 * tid, e1 = 2 * tid + 1;
    const int t0 = e0 >> 4, j0 = e0 & 15, k0 = j0 + (j0 >= P);
    const int t1 = e1 >> 4, j1 = e1 & 15, k1 = j1 + (j1 >= P);
    // nx==0 -> emb row 0 all-zero -> product 0 regardless of weight value
    float w0  = __ldcg(ew + (size_t)NX_s[t0 + P] * VOCAB + NX_s[t0 + k0]);
    float w1  = __ldcg(ew + (size_t)NX_s[t1 + P] * VOCAB + NX_s[t1 + k1]);
    float nnv = (tid < T) ? __ldca(nw + NX_s[tid + P]) : 0.f;

    // ---- register window (17) + prefetch ring (D): 21 L2-hit LDGs in flight ----
    float win[17];
    #pragma unroll
    for (int k = 0; k < 17; k++)
        win[k] = emb[(size_t)NX_s[k] * C + ct];
    float pf[D];
    #pragma unroll
    for (int d = 0; d < D; d++)
        pf[d] = emb[(size_t)NX_s[17 + d] * C + ct];

    // STS waits on the gather scoreboard -- latency already overlapped above
    W_s[e0] = w0;
    W_s[e1] = w1;
    if (tid < T) NN_s[tid] = nnv;
    __syncthreads();

    float acc = 0.f;
    float4 wa = ((const float4*)W_s)[0];
    float4 wb = ((const float4*)W_s)[1];
    float nn  = NN_s[0];

    #pragma unroll
    for (int tt = 0; tt < T; tt++) {
        // emb prefetch: issued D+1 iters before first read
        int r = 17 + D + tt; if (r > ROWS - 1) r = ROWS - 1;   // clamped tail
        float newv = emb[(size_t)NX_s[r] * C + ct];

        // wc/wd loaded now, consumed >=20 instrs later (LDS latency hidden)
        const float4* wvt = (const float4*)(W_s + tt * 16);
        float4 wc = wvt[2], wd = wvt[3];

        float m0 = win[tt % 17]       * wa.x;     // j=0 (no max needed)
        float m1 = win[(tt + 1) % 17] * wa.y;     // j=1
        #define STEP(j, wreg, m) m = fmaxf(m, win[(tt + (j) + ((j) >= 8)) % 17] * (wreg));
        STEP(2,  wa.z, m0) STEP(3,  wa.w, m1)
        STEP(4,  wb.x, m0) STEP(5,  wb.y, m1) STEP(6,  wb.z, m0) STEP(7,  wb.w, m1)
        STEP(8,  wc.x, m0) STEP(9,  wc.y, m1) STEP(10, wc.z, m0) STEP(11, wc.w, m1)
        STEP(12, wd.x, m0) STEP(13, wd.y, m1) STEP(14, wd.z, m0) STEP(15, wd.w, m1)
        #undef STEP
        float m = fmaxf(m0, m1);

        float rn = win[(tt + 8) % 17];
        acc += fmaf(nn, rn - m, m);               // (1-nn)*m + nn*rn

        if (tt + 1 < T) {                         // prefetch next wa/wb/nn
            const float4* wvn = (const float4*)(W_s + (tt + 1) * 16);
            wa = wvn[0];
            wb = wvn[1];
            nn = NN_s[tt + 1];
        }

        // slide window through prefetch ring (fully unrolled -> register renaming)
        win[tt % 17] = pf[0];
        #pragma unroll
        for (int d = 0; d < D - 1; d++) pf[d] = pf[d + 1];
        pf[D - 1] = newv;
    }

    atomicAdd(&out[b * C + ct], acc);
}

extern "C" void kernel_launch(void* const* d_in, const int* in_sizes, int n_in,
                              void* d_out, int out_size) {
    const int*   ids = (const int*)  d_in[0];
    const float* emb = (const float*)d_in[1];
    const float* ew  = (const float*)d_in[2];
    const float* nw  = (const float*)d_in[3];
    float* out = (float*)d_out;

    // graph memset node zeroes d_out (poisoned to 0xAA by the harness)
    cudaMemsetAsync(out, 0, (size_t)out_size * sizeof(float));

    dim3 grid(LL / T, BB);
    gnn_kernel<<<grid, THREADS>>>(ids, emb, ew, nw, out);
}